// round 16
// baseline (speedup 1.0000x reference)
#include <cuda_runtime.h>
#include <cuda_fp16.h>
#include <math_constants.h>
#include <cstdint>

#define DIN  256
#define DOUT 128
#define NMAX 100000
#define EMAX 3200000
#define ALPHA 0.2f
#define LOG2E 1.4426950408889634f
#define WCONV_BLOCKS 128

// ---- scratch (static device globals; no allocation) ----
__device__ __half  g_seqh[(size_t)NMAX * DOUT]; // seq_fts (fp16 storage)
__device__ __half  g_Wh[DOUT * DIN];            // W transposed [n][k], fp16
__device__ float   g_f1[NMAX];                  // log2e * (f1 + al_b)
__device__ float   g_f2[NMAX];                  // log2e * (f2 + ar_b)
__device__ int     g_cnt[NMAX];                 // zero at call entry (self-cleaning)
__device__ int     g_off[NMAX];
__device__ int     g_cur[NMAX];
__device__ int     g_bsum[512];
__device__ __align__(16) float2 g_epair[EMAX];  // CSR: (col bits, e = 2^leaky)

// ---------------------------------------------------------------------------
// combo1: blocks [0,128)   -> W transpose + fp16 convert
//         blocks [128,...) -> edge pass 1: per-row edge count (x4)
__global__ void k_combo1(const float* __restrict__ W,
                         const int* __restrict__ row, int e) {
    if (blockIdx.x < WCONV_BLOCKS) {
        int idx = blockIdx.x * blockDim.x + threadIdx.x;   // 0..32767
        int nn = idx >> 8;
        int kk = idx & 255;
        g_Wh[idx] = __float2half_rn(W[kk * DOUT + nn]);
    } else {
        int bi = blockIdx.x - WCONV_BLOCKS;
        int i = (bi * blockDim.x + threadIdx.x) * 4;
        if (i + 4 <= e) {
            int4 r4 = *(const int4*)(row + i);
            atomicAdd(&g_cnt[r4.x], 1);
            atomicAdd(&g_cnt[r4.y], 1);
            atomicAdd(&g_cnt[r4.z], 1);
            atomicAdd(&g_cnt[r4.w], 1);
        } else {
            for (int k = i; k < e; k++) atomicAdd(&g_cnt[row[k]], 1);
        }
    }
}

// ---------------------------------------------------------------------------
// scan1: block-local exclusive scan of g_cnt -> g_off; resets g_cnt.
__global__ void k_scan1(int n) {
    __shared__ int sh[256];
    int t = threadIdx.x;
    int i = blockIdx.x * 256 + t;
    int v = (i < n) ? g_cnt[i] : 0;
    sh[t] = v;
    __syncthreads();
    #pragma unroll
    for (int o = 1; o < 256; o <<= 1) {
        int x = (t >= o) ? sh[t - o] : 0;
        __syncthreads();
        sh[t] += x;
        __syncthreads();
    }
    if (i < n) { g_off[i] = sh[t] - v; g_cnt[i] = 0; }
    if (t == 255) g_bsum[blockIdx.x] = sh[255];
}

// ---------------------------------------------------------------------------
// combo2: blocks [0,GB)  -> fp16 HMMA GEMM (128x128 tile) + f1/f2 epilogue
//         blocks [GB,..) -> scan23 (block-sum prefix + finalize off/cur)
// Legal concurrency: GEMM needs only g_Wh (combo1); scan23 needs only
// g_off/g_bsum (scan1). Neither reads the other's outputs.
#define HSTR 40
__global__ __launch_bounds__(256) void k_combo2(const float* __restrict__ A,
                                                const float* __restrict__ al_w,
                                                const float* __restrict__ al_b,
                                                const float* __restrict__ ar_w,
                                                const float* __restrict__ ar_b,
                                                int n, int nblk, int GB) {
    if (blockIdx.x >= GB) {
        // ---------------- scan23 (512 nodes per block) ----------------
        __shared__ int sh2[512];
        int bi = blockIdx.x - GB;
        int t = threadIdx.x;                 // 0..255; emulate 512 via x2
        // scan block sums with 256 threads over <=512 entries (two-step)
        // load into sh2[0..511]
        sh2[t]       = (t < nblk)       ? g_bsum[t]       : 0;
        sh2[t + 256] = (t + 256 < nblk) ? g_bsum[t + 256] : 0;
        __syncthreads();
        // Hillis-Steele over 512 entries using 256 threads (2 elems each)
        #pragma unroll
        for (int o = 1; o < 512; o <<= 1) {
            int a0 = (t >= o)       ? sh2[t - o]       : 0;
            int a1 = (t + 256 >= o) ? sh2[t + 256 - o] : 0;
            __syncthreads();
            sh2[t] += a0;
            sh2[t + 256] += a1;
            __syncthreads();
        }
        // exclusive: shift right by one
        int i0 = bi * 512 + t;
        int i1 = i0 + 256;
        if (i0 < n) {
            int blk = i0 >> 8;
            int pre = (blk == 0) ? 0 : sh2[blk - 1];
            int o = g_off[i0] + pre;
            g_off[i0] = o; g_cur[i0] = o;
        }
        if (i1 < n) {
            int blk = i1 >> 8;
            int pre = (blk == 0) ? 0 : sh2[blk - 1];
            int o = g_off[i1] + pre;
            g_off[i1] = o; g_cur[i1] = o;
        }
        return;
    }

    // ---------------- GEMM: 128 rows x 128 cols per block ----------------
    __shared__ __half As[128 * HSTR];   // [m][k]
    __shared__ __half Bs[128 * HSTR];   // [n][k]

    int tid  = threadIdx.x;
    int wid  = tid >> 5;
    int lane = tid & 31;
    int warp_m = wid & 3;
    int warp_n = wid >> 2;
    int group  = lane >> 2;
    int tig    = lane & 3;
    int rowBase = blockIdx.x * 128;

    float acc[2][8][4];
    #pragma unroll
    for (int mt = 0; mt < 2; mt++)
        #pragma unroll
        for (int nt = 0; nt < 8; nt++)
            #pragma unroll
            for (int q = 0; q < 4; q++) acc[mt][nt][q] = 0.0f;

    for (int k0 = 0; k0 < DIN; k0 += 32) {
        #pragma unroll
        for (int i = 0; i < 4; i++) {
            int idx = tid + 256 * i;
            int m   = idx >> 3;
            int q   = idx & 7;
            int gr  = rowBase + m;
            float4 v = make_float4(0.f, 0.f, 0.f, 0.f);
            if (gr < n) v = *(const float4*)(A + (size_t)gr * DIN + k0 + q * 4);
            __half2 h0 = __floats2half2_rn(v.x, v.y);
            __half2 h1 = __floats2half2_rn(v.z, v.w);
            uint2 u;
            u.x = *reinterpret_cast<uint32_t*>(&h0);
            u.y = *reinterpret_cast<uint32_t*>(&h1);
            *(uint2*)&As[m * HSTR + q * 4] = u;
        }
        #pragma unroll
        for (int i = 0; i < 2; i++) {
            int idx = tid + 256 * i;
            int nn  = idx >> 2;
            int q   = idx & 3;
            *(uint4*)&Bs[nn * HSTR + q * 8] =
                *(const uint4*)(g_Wh + nn * DIN + k0 + q * 8);
        }
        __syncthreads();

        #pragma unroll
        for (int ks = 0; ks < 2; ks++) {
            int kb = ks * 16;
            uint32_t af[2][4];
            #pragma unroll
            for (int mt = 0; mt < 2; mt++) {
                int m = warp_m * 32 + mt * 16 + group;
                const __half* pr0 = &As[m * HSTR + kb + tig * 2];
                const __half* pr1 = &As[(m + 8) * HSTR + kb + tig * 2];
                af[mt][0] = *(const uint32_t*)(pr0);
                af[mt][1] = *(const uint32_t*)(pr1);
                af[mt][2] = *(const uint32_t*)(pr0 + 8);
                af[mt][3] = *(const uint32_t*)(pr1 + 8);
            }
            uint32_t bf[8][2];
            #pragma unroll
            for (int nt = 0; nt < 8; nt++) {
                int nn = warp_n * 64 + nt * 8 + group;
                const __half* pb = &Bs[nn * HSTR + kb + tig * 2];
                bf[nt][0] = *(const uint32_t*)(pb);
                bf[nt][1] = *(const uint32_t*)(pb + 8);
            }
            #pragma unroll
            for (int mt = 0; mt < 2; mt++)
                #pragma unroll
                for (int nt = 0; nt < 8; nt++) {
                    asm volatile(
                        "mma.sync.aligned.m16n8k16.row.col.f32.f16.f16.f32 "
                        "{%0,%1,%2,%3}, {%4,%5,%6,%7}, {%8,%9}, {%0,%1,%2,%3};"
                        : "+f"(acc[mt][nt][0]), "+f"(acc[mt][nt][1]),
                          "+f"(acc[mt][nt][2]), "+f"(acc[mt][nt][3])
                        : "r"(af[mt][0]), "r"(af[mt][1]), "r"(af[mt][2]), "r"(af[mt][3]),
                          "r"(bf[nt][0]), "r"(bf[nt][1]));
                }
        }
        __syncthreads();
    }

    // store seq_fts as fp16
    #pragma unroll
    for (int mt = 0; mt < 2; mt++) {
        int r0 = rowBase + warp_m * 32 + mt * 16 + group;
        #pragma unroll
        for (int nt = 0; nt < 8; nt++) {
            int cc = warp_n * 64 + nt * 8 + tig * 2;
            if (r0 < n)
                *(__half2*)(g_seqh + (size_t)r0 * DOUT + cc) =
                    __floats2half2_rn(acc[mt][nt][0], acc[mt][nt][1]);
            if (r0 + 8 < n)
                *(__half2*)(g_seqh + (size_t)(r0 + 8) * DOUT + cc) =
                    __floats2half2_rn(acc[mt][nt][2], acc[mt][nt][3]);
        }
    }

    // fused f1/f2 epilogue: store log2e * (dot + bias)
    float awv[16], rwv[16];
    #pragma unroll
    for (int nt = 0; nt < 8; nt++) {
        int cc = warp_n * 64 + nt * 8 + tig * 2;
        float2 a2 = *(const float2*)(al_w + cc);
        float2 r2 = *(const float2*)(ar_w + cc);
        awv[nt * 2] = a2.x; awv[nt * 2 + 1] = a2.y;
        rwv[nt * 2] = r2.x; rwv[nt * 2 + 1] = r2.y;
    }

    float* smf = (float*)&As[0];
    float p1[2][2], p2[2][2];
    #pragma unroll
    for (int mt = 0; mt < 2; mt++) {
        #pragma unroll
        for (int half = 0; half < 2; half++) {
            float s1 = 0.f, s2 = 0.f;
            #pragma unroll
            for (int nt = 0; nt < 8; nt++) {
                float v0 = acc[mt][nt][half * 2];
                float v1 = acc[mt][nt][half * 2 + 1];
                s1 += v0 * awv[nt * 2] + v1 * awv[nt * 2 + 1];
                s2 += v0 * rwv[nt * 2] + v1 * rwv[nt * 2 + 1];
            }
            s1 += __shfl_xor_sync(0xFFFFFFFFu, s1, 1);
            s1 += __shfl_xor_sync(0xFFFFFFFFu, s1, 2);
            s2 += __shfl_xor_sync(0xFFFFFFFFu, s2, 1);
            s2 += __shfl_xor_sync(0xFFFFFFFFu, s2, 2);
            p1[mt][half] = s1; p2[mt][half] = s2;
        }
    }
    __syncthreads();
    if (warp_n == 0 && tig == 0) {
        #pragma unroll
        for (int mt = 0; mt < 2; mt++)
            #pragma unroll
            for (int half = 0; half < 2; half++) {
                int lr = warp_m * 32 + mt * 16 + group + half * 8;
                smf[lr]       = p1[mt][half];
                smf[128 + lr] = p2[mt][half];
            }
    }
    __syncthreads();
    if (warp_n == 1 && tig == 0) {
        float ab = al_b[0], rb = ar_b[0];
        #pragma unroll
        for (int mt = 0; mt < 2; mt++)
            #pragma unroll
            for (int half = 0; half < 2; half++) {
                int lr = warp_m * 32 + mt * 16 + group + half * 8;
                int gr = rowBase + lr;
                if (gr < n) {
                    g_f1[gr] = LOG2E * (smf[lr]       + p1[mt][half] + ab);
                    g_f2[gr] = LOG2E * (smf[128 + lr] + p2[mt][half] + rb);
                }
            }
    }
}

// ---------------------------------------------------------------------------
// edge2 (standalone, AFTER gemm): e_j = 2^max(t, 0.2t); scatter (col, e)
__global__ void k_edge2(const int* __restrict__ row, const int* __restrict__ col, int e) {
    int i = (blockIdx.x * blockDim.x + threadIdx.x) * 4;
    if (i + 4 <= e) {
        int4 r4 = *(const int4*)(row + i);
        int4 c4 = *(const int4*)(col + i);
        float t0 = __ldg(&g_f1[r4.x]) + __ldg(&g_f2[c4.x]);
        float t1 = __ldg(&g_f1[r4.y]) + __ldg(&g_f2[c4.y]);
        float t2 = __ldg(&g_f1[r4.z]) + __ldg(&g_f2[c4.z]);
        float t3 = __ldg(&g_f1[r4.w]) + __ldg(&g_f2[c4.w]);
        float e0 = exp2f(fmaxf(t0, ALPHA * t0));
        float e1 = exp2f(fmaxf(t1, ALPHA * t1));
        float e2 = exp2f(fmaxf(t2, ALPHA * t2));
        float e3 = exp2f(fmaxf(t3, ALPHA * t3));
        int p0 = atomicAdd(&g_cur[r4.x], 1);
        int p1 = atomicAdd(&g_cur[r4.y], 1);
        int p2 = atomicAdd(&g_cur[r4.z], 1);
        int p3 = atomicAdd(&g_cur[r4.w], 1);
        g_epair[p0] = make_float2(__int_as_float(c4.x), e0);
        g_epair[p1] = make_float2(__int_as_float(c4.y), e1);
        g_epair[p2] = make_float2(__int_as_float(c4.z), e2);
        g_epair[p3] = make_float2(__int_as_float(c4.w), e3);
    } else {
        for (int k = i; k < e; k++) {
            int r = row[k], c = col[k];
            float t = __ldg(&g_f1[r]) + __ldg(&g_f2[c]);
            float ev = exp2f(fmaxf(t, ALPHA * t));
            int p = atomicAdd(&g_cur[r], 1);
            g_epair[p] = make_float2(__int_as_float(c), ev);
        }
    }
}

// ---------------------------------------------------------------------------
// spmm: CSR SpMM, one warp per node. Pure loads + FFMA (exp precomputed).
__global__ __launch_bounds__(256) void k_spmm(const float* __restrict__ bias,
                                              float* __restrict__ out, int n) {
    int gw   = (blockIdx.x * blockDim.x + threadIdx.x) >> 5;
    int lane = threadIdx.x & 31;
    if (gw >= n) return;
    int j0  = __ldg(&g_off[gw]);
    int end = __ldg(&g_cur[gw]);
    int j   = j0;

    float4 acc = make_float4(0.f, 0.f, 0.f, 0.f);
    float ssum = 0.0f;
    const uint2* lanebase = ((const uint2*)g_seqh) + lane;   // +c*32 per row

    // scalar peel: float4 loads on g_epair need even j
    if (j < end && (j & 1)) {
        float2 p = __ldg((const float2*)(g_epair + j));
        int c = __float_as_int(p.x);
        float ev = p.y;
        ssum += ev;
        uint2 u = __ldg(lanebase + ((size_t)c << 5));
        float2 a = __half22float2(*reinterpret_cast<__half2*>(&u.x));
        float2 b = __half22float2(*reinterpret_cast<__half2*>(&u.y));
        acc.x += ev * a.x; acc.y += ev * a.y;
        acc.z += ev * b.x; acc.w += ev * b.y;
        j++;
    }

    for (; j + 4 <= end; j += 4) {
        float4 pa = __ldg((const float4*)(g_epair + j));      // edges j, j+1
        float4 pb = __ldg((const float4*)(g_epair + j + 2));  // edges j+2, j+3
        int c0 = __float_as_int(pa.x), c1 = __float_as_int(pa.z);
        int c2 = __float_as_int(pb.x), c3 = __float_as_int(pb.z);
        float e0 = pa.y, e1 = pa.w, e2 = pb.y, e3 = pb.w;
        uint2 u0 = __ldg(lanebase + ((size_t)c0 << 5));
        uint2 u1 = __ldg(lanebase + ((size_t)c1 << 5));
        uint2 u2 = __ldg(lanebase + ((size_t)c2 << 5));
        uint2 u3 = __ldg(lanebase + ((size_t)c3 << 5));
        ssum += (e0 + e1) + (e2 + e3);
        float2 a0 = __half22float2(*reinterpret_cast<__half2*>(&u0.x));
        float2 b0 = __half22float2(*reinterpret_cast<__half2*>(&u0.y));
        float2 a1 = __half22float2(*reinterpret_cast<__half2*>(&u1.x));
        float2 b1 = __half22float2(*reinterpret_cast<__half2*>(&u1.y));
        float2 a2 = __half22float2(*reinterpret_cast<__half2*>(&u2.x));
        float2 b2 = __half22float2(*reinterpret_cast<__half2*>(&u2.y));
        float2 a3 = __half22float2(*reinterpret_cast<__half2*>(&u3.x));
        float2 b3 = __half22float2(*reinterpret_cast<__half2*>(&u3.y));
        acc.x += e0 * a0.x + e1 * a1.x + e2 * a2.x + e3 * a3.x;
        acc.y += e0 * a0.y + e1 * a1.y + e2 * a2.y + e3 * a3.y;
        acc.z += e0 * b0.x + e1 * b1.x + e2 * b2.x + e3 * b3.x;
        acc.w += e0 * b0.y + e1 * b1.y + e2 * b2.y + e3 * b3.y;
    }
    for (; j < end; j++) {
        float2 p = __ldg((const float2*)(g_epair + j));
        int c = __float_as_int(p.x);
        float ev = p.y;
        ssum += ev;
        uint2 u = __ldg(lanebase + ((size_t)c << 5));
        float2 a = __half22float2(*reinterpret_cast<__half2*>(&u.x));
        float2 b = __half22float2(*reinterpret_cast<__half2*>(&u.y));
        acc.x += ev * a.x; acc.y += ev * a.y;
        acc.z += ev * b.x; acc.w += ev * b.y;
    }

    float inv = (end > j0) ? 1.0f / ssum : 0.0f;
    float4 b = ((const float4*)bias)[lane];
    acc.x = acc.x * inv + b.x;
    acc.y = acc.y * inv + b.y;
    acc.z = acc.z * inv + b.z;
    acc.w = acc.w * inv + b.w;
    ((float4*)(out + (size_t)gw * DOUT))[lane] = acc;
}

// ---------------------------------------------------------------------------
extern "C" void kernel_launch(void* const* d_in, const int* in_sizes, int n_in,
                              void* d_out, int out_size) {
    const float* feat = (const float*)d_in[0];
    const int*   row  = (const int*)  d_in[1];
    const int*   col  = (const int*)  d_in[2];
    const float* W    = (const float*)d_in[3];
    const float* al_w = (const float*)d_in[4];
    const float* al_b = (const float*)d_in[5];
    const float* ar_w = (const float*)d_in[6];
    const float* ar_b = (const float*)d_in[7];
    const float* bias = (const float*)d_in[8];
    float* out = (float*)d_out;

    int n = in_sizes[0] / DIN;   // 100000
    int e = in_sizes[1];         // 3200000
    int nblk  = (n + 255) / 256;         // scan1 blocks (391 <= 512)
    int eblk  = (e / 4 + 255) / 256;     // edge-pass blocks (3125)
    int GB    = (n + 127) / 128;         // gemm blocks (782)
    int SB    = (n + 511) / 512;         // scan23 blocks (196)

    k_combo1<<<WCONV_BLOCKS + eblk, 256>>>(W, row, e);            // wconv ∥ edge1
    k_scan1<<<nblk, 256>>>(n);
    k_combo2<<<GB + SB, 256>>>(feat, al_w, al_b, ar_w, ar_b,      // gemm ∥ scan23
                               n, nblk, GB);
    k_edge2<<<eblk, 256>>>(row, col, e);                          // exp + scatter
    k_spmm<<<(n * 32 + 255) / 256, 256>>>(bias, out, n);
}

// round 17
// speedup vs baseline: 1.0558x; 1.0558x over previous
#include <cuda_runtime.h>
#include <cuda_fp16.h>
#include <math_constants.h>
#include <cstdint>

#define DIN  256
#define DOUT 128
#define NMAX 100000
#define EMAX 3200000
#define ALPHA 0.2f
#define LOG2E 1.4426950408889634f
#define WCONV_BLOCKS 128

// ---- scratch (static device globals; no allocation) ----
__device__ __half  g_seqh[(size_t)NMAX * DOUT]; // seq_fts (fp16 storage)
__device__ __half  g_Wh[DOUT * DIN];            // W transposed [n][k], fp16
__device__ float   g_f1[NMAX];                  // log2e * (f1 + al_b)
__device__ float   g_f2[NMAX];                  // log2e * (f2 + ar_b)
__device__ int     g_cnt[NMAX];                 // zero at call entry (self-cleaning)
__device__ int     g_off[NMAX];
__device__ int     g_cur[NMAX];
__device__ int     g_bsum[512];
__device__ int     g_ecol[EMAX];

// lane reads 4 halves (8B) of a 128-col fp16 row, returns as float4
__device__ __forceinline__ float4 ldrow_h(const __half* base, int lane) {
    uint2 u = __ldg(((const uint2*)base) + lane);
    __half2 h0 = *reinterpret_cast<__half2*>(&u.x);
    __half2 h1 = *reinterpret_cast<__half2*>(&u.y);
    float2 a = __half22float2(h0);
    float2 b = __half22float2(h1);
    return make_float4(a.x, a.y, b.x, b.y);
}

// e = 2^max(t, alpha*t)  ==  exp(leaky_relu(x))  when t = log2e*x
__device__ __forceinline__ float edge_e(float t) {
    float a = fmaxf(t, ALPHA * t);
    float r;
    asm("ex2.approx.f32 %0, %1;" : "=f"(r) : "f"(a));
    return r;
}

// ---------------------------------------------------------------------------
// combo1: blocks [0,128)   -> W transpose + fp16 convert
//         blocks [128,...) -> edge pass 1: per-row edge count (x4)
__global__ void k_combo1(const float* __restrict__ W,
                         const int* __restrict__ row, int e) {
    if (blockIdx.x < WCONV_BLOCKS) {
        int idx = blockIdx.x * blockDim.x + threadIdx.x;   // 0..32767
        int nn = idx >> 8;
        int kk = idx & 255;
        g_Wh[idx] = __float2half_rn(W[kk * DOUT + nn]);
    } else {
        int bi = blockIdx.x - WCONV_BLOCKS;
        int i = (bi * blockDim.x + threadIdx.x) * 4;
        if (i + 4 <= e) {
            int4 r4 = *(const int4*)(row + i);
            atomicAdd(&g_cnt[r4.x], 1);
            atomicAdd(&g_cnt[r4.y], 1);
            atomicAdd(&g_cnt[r4.z], 1);
            atomicAdd(&g_cnt[r4.w], 1);
        } else {
            for (int k = i; k < e; k++) atomicAdd(&g_cnt[row[k]], 1);
        }
    }
}

// ---------------------------------------------------------------------------
// scan1: block-local exclusive scan of g_cnt -> g_off; resets g_cnt.
__global__ void k_scan1(int n) {
    __shared__ int sh[256];
    int t = threadIdx.x;
    int i = blockIdx.x * 256 + t;
    int v = (i < n) ? g_cnt[i] : 0;
    sh[t] = v;
    __syncthreads();
    #pragma unroll
    for (int o = 1; o < 256; o <<= 1) {
        int x = (t >= o) ? sh[t - o] : 0;
        __syncthreads();
        sh[t] += x;
        __syncthreads();
    }
    if (i < n) { g_off[i] = sh[t] - v; g_cnt[i] = 0; }
    if (t == 255) g_bsum[blockIdx.x] = sh[255];
}

// scan23: every block redundantly scans the block sums, adds prefix.
__global__ void k_scan23(int n, int nblk) {
    __shared__ int sh[512];
    int t = threadIdx.x;
    int v = (t < nblk) ? g_bsum[t] : 0;
    sh[t] = v;
    __syncthreads();
    #pragma unroll
    for (int o = 1; o < 512; o <<= 1) {
        int x = (t >= o) ? sh[t - o] : 0;
        __syncthreads();
        sh[t] += x;
        __syncthreads();
    }
    int ex = sh[t] - v;
    __syncthreads();
    sh[t] = ex;
    __syncthreads();
    int i = blockIdx.x * 512 + t;
    if (i < n) {
        int o = g_off[i] + sh[i >> 8];
        g_off[i] = o;
        g_cur[i] = o;
    }
}

// ---------------------------------------------------------------------------
// combo2: blocks [0,GB)  -> fp16 HMMA GEMM (128x128 tile) + f1/f2 epilogue
//         blocks [GB,..) -> edge pass 2 (CSR scatter of col, x4)
#define HSTR 40
__global__ __launch_bounds__(256) void k_combo2(const float* __restrict__ A,
                                                const float* __restrict__ al_w,
                                                const float* __restrict__ al_b,
                                                const float* __restrict__ ar_w,
                                                const float* __restrict__ ar_b,
                                                const int* __restrict__ row,
                                                const int* __restrict__ col,
                                                int n, int e, int GB) {
    if (blockIdx.x >= GB) {
        int bi = blockIdx.x - GB;
        int i = (bi * blockDim.x + threadIdx.x) * 4;
        if (i + 4 <= e) {
            int4 r4 = *(const int4*)(row + i);
            int4 c4 = *(const int4*)(col + i);
            int p0 = atomicAdd(&g_cur[r4.x], 1);
            int p1 = atomicAdd(&g_cur[r4.y], 1);
            int p2 = atomicAdd(&g_cur[r4.z], 1);
            int p3 = atomicAdd(&g_cur[r4.w], 1);
            g_ecol[p0] = c4.x; g_ecol[p1] = c4.y;
            g_ecol[p2] = c4.z; g_ecol[p3] = c4.w;
        } else {
            for (int k = i; k < e; k++) {
                int p = atomicAdd(&g_cur[row[k]], 1);
                g_ecol[p] = col[k];
            }
        }
        return;
    }

    // ---------------- GEMM: 128 rows x 128 cols per block ----------------
    __shared__ __half As[128 * HSTR];   // [m][k]
    __shared__ __half Bs[128 * HSTR];   // [n][k]

    int tid  = threadIdx.x;
    int wid  = tid >> 5;
    int lane = tid & 31;
    int warp_m = wid & 3;
    int warp_n = wid >> 2;
    int group  = lane >> 2;
    int tig    = lane & 3;
    int rowBase = blockIdx.x * 128;

    float acc[2][8][4];
    #pragma unroll
    for (int mt = 0; mt < 2; mt++)
        #pragma unroll
        for (int nt = 0; nt < 8; nt++)
            #pragma unroll
            for (int q = 0; q < 4; q++) acc[mt][nt][q] = 0.0f;

    for (int k0 = 0; k0 < DIN; k0 += 32) {
        #pragma unroll
        for (int i = 0; i < 4; i++) {
            int idx = tid + 256 * i;
            int m   = idx >> 3;
            int q   = idx & 7;
            int gr  = rowBase + m;
            float4 v = make_float4(0.f, 0.f, 0.f, 0.f);
            if (gr < n) v = *(const float4*)(A + (size_t)gr * DIN + k0 + q * 4);
            __half2 h0 = __floats2half2_rn(v.x, v.y);
            __half2 h1 = __floats2half2_rn(v.z, v.w);
            uint2 u;
            u.x = *reinterpret_cast<uint32_t*>(&h0);
            u.y = *reinterpret_cast<uint32_t*>(&h1);
            *(uint2*)&As[m * HSTR + q * 4] = u;
        }
        #pragma unroll
        for (int i = 0; i < 2; i++) {
            int idx = tid + 256 * i;
            int nn  = idx >> 2;
            int q   = idx & 3;
            *(uint4*)&Bs[nn * HSTR + q * 8] =
                *(const uint4*)(g_Wh + nn * DIN + k0 + q * 8);
        }
        __syncthreads();

        #pragma unroll
        for (int ks = 0; ks < 2; ks++) {
            int kb = ks * 16;
            uint32_t af[2][4];
            #pragma unroll
            for (int mt = 0; mt < 2; mt++) {
                int m = warp_m * 32 + mt * 16 + group;
                const __half* pr0 = &As[m * HSTR + kb + tig * 2];
                const __half* pr1 = &As[(m + 8) * HSTR + kb + tig * 2];
                af[mt][0] = *(const uint32_t*)(pr0);
                af[mt][1] = *(const uint32_t*)(pr1);
                af[mt][2] = *(const uint32_t*)(pr0 + 8);
                af[mt][3] = *(const uint32_t*)(pr1 + 8);
            }
            uint32_t bf[8][2];
            #pragma unroll
            for (int nt = 0; nt < 8; nt++) {
                int nn = warp_n * 64 + nt * 8 + group;
                const __half* pb = &Bs[nn * HSTR + kb + tig * 2];
                bf[nt][0] = *(const uint32_t*)(pb);
                bf[nt][1] = *(const uint32_t*)(pb + 8);
            }
            #pragma unroll
            for (int mt = 0; mt < 2; mt++)
                #pragma unroll
                for (int nt = 0; nt < 8; nt++) {
                    asm volatile(
                        "mma.sync.aligned.m16n8k16.row.col.f32.f16.f16.f32 "
                        "{%0,%1,%2,%3}, {%4,%5,%6,%7}, {%8,%9}, {%0,%1,%2,%3};"
                        : "+f"(acc[mt][nt][0]), "+f"(acc[mt][nt][1]),
                          "+f"(acc[mt][nt][2]), "+f"(acc[mt][nt][3])
                        : "r"(af[mt][0]), "r"(af[mt][1]), "r"(af[mt][2]), "r"(af[mt][3]),
                          "r"(bf[nt][0]), "r"(bf[nt][1]));
                }
        }
        __syncthreads();
    }

    // store seq_fts as fp16
    #pragma unroll
    for (int mt = 0; mt < 2; mt++) {
        int r0 = rowBase + warp_m * 32 + mt * 16 + group;
        #pragma unroll
        for (int nt = 0; nt < 8; nt++) {
            int cc = warp_n * 64 + nt * 8 + tig * 2;
            if (r0 < n)
                *(__half2*)(g_seqh + (size_t)r0 * DOUT + cc) =
                    __floats2half2_rn(acc[mt][nt][0], acc[mt][nt][1]);
            if (r0 + 8 < n)
                *(__half2*)(g_seqh + (size_t)(r0 + 8) * DOUT + cc) =
                    __floats2half2_rn(acc[mt][nt][2], acc[mt][nt][3]);
        }
    }

    // fused f1/f2 epilogue: store log2e-scaled values (spmm uses ex2)
    float awv[16], rwv[16];
    #pragma unroll
    for (int nt = 0; nt < 8; nt++) {
        int cc = warp_n * 64 + nt * 8 + tig * 2;
        float2 a2 = *(const float2*)(al_w + cc);
        float2 r2 = *(const float2*)(ar_w + cc);
        awv[nt * 2] = a2.x; awv[nt * 2 + 1] = a2.y;
        rwv[nt * 2] = r2.x; rwv[nt * 2 + 1] = r2.y;
    }

    float* smf = (float*)&As[0];
    float p1[2][2], p2[2][2];
    #pragma unroll
    for (int mt = 0; mt < 2; mt++) {
        #pragma unroll
        for (int half = 0; half < 2; half++) {
            float s1 = 0.f, s2 = 0.f;
            #pragma unroll
            for (int nt = 0; nt < 8; nt++) {
                float v0 = acc[mt][nt][half * 2];
                float v1 = acc[mt][nt][half * 2 + 1];
                s1 += v0 * awv[nt * 2] + v1 * awv[nt * 2 + 1];
                s2 += v0 * rwv[nt * 2] + v1 * rwv[nt * 2 + 1];
            }
            s1 += __shfl_xor_sync(0xFFFFFFFFu, s1, 1);
            s1 += __shfl_xor_sync(0xFFFFFFFFu, s1, 2);
            s2 += __shfl_xor_sync(0xFFFFFFFFu, s2, 1);
            s2 += __shfl_xor_sync(0xFFFFFFFFu, s2, 2);
            p1[mt][half] = s1; p2[mt][half] = s2;
        }
    }
    __syncthreads();
    if (warp_n == 0 && tig == 0) {
        #pragma unroll
        for (int mt = 0; mt < 2; mt++)
            #pragma unroll
            for (int half = 0; half < 2; half++) {
                int lr = warp_m * 32 + mt * 16 + group + half * 8;
                smf[lr]       = p1[mt][half];
                smf[128 + lr] = p2[mt][half];
            }
    }
    __syncthreads();
    if (warp_n == 1 && tig == 0) {
        float ab = al_b[0], rb = ar_b[0];
        #pragma unroll
        for (int mt = 0; mt < 2; mt++)
            #pragma unroll
            for (int half = 0; half < 2; half++) {
                int lr = warp_m * 32 + mt * 16 + group + half * 8;
                int gr = rowBase + lr;
                if (gr < n) {
                    g_f1[gr] = LOG2E * (smf[lr]       + p1[mt][half] + ab);
                    g_f2[gr] = LOG2E * (smf[128 + lr] + p2[mt][half] + rb);
                }
            }
    }
}

// ---------------------------------------------------------------------------
#define EDGE_ACC(c, ev)                                                     \
    do {                                                                    \
        float4 _v = ldrow_h(g_seqh + (size_t)(c) * DOUT, lane);             \
        acc.x += (ev) * _v.x; acc.y += (ev) * _v.y;                         \
        acc.z += (ev) * _v.z; acc.w += (ev) * _v.w;                         \
    } while (0)

// spmm: CSR SpMM + fused softmax, one warp per node, 8-edge main loop.
// exp via ex2.approx on pre-scaled logits; leaky via single FMNMX.
__global__ __launch_bounds__(256) void k_spmm(const float* __restrict__ bias,
                                              float* __restrict__ out, int n) {
    int gw   = (blockIdx.x * blockDim.x + threadIdx.x) >> 5;
    int lane = threadIdx.x & 31;
    if (gw >= n) return;
    int j0  = __ldg(&g_off[gw]);
    int end = __ldg(&g_cur[gw]);
    int j   = j0;

    float f1v = __ldg(&g_f1[gw]);
    float4 acc = make_float4(0.f, 0.f, 0.f, 0.f);
    float ssum = 0.0f;

    while (j < end && (j & 3)) {
        int c = __ldg(&g_ecol[j]);
        float ev = edge_e(f1v + __ldg(&g_f2[c]));
        ssum += ev;
        EDGE_ACC(c, ev);
        j++;
    }

    for (; j + 8 <= end; j += 8) {
        int4 ca = __ldg((const int4*)(g_ecol + j));
        int4 cb = __ldg((const int4*)(g_ecol + j + 4));
        float w0 = __ldg(&g_f2[ca.x]), w1 = __ldg(&g_f2[ca.y]);
        float w2 = __ldg(&g_f2[ca.z]), w3 = __ldg(&g_f2[ca.w]);
        float w4 = __ldg(&g_f2[cb.x]), w5 = __ldg(&g_f2[cb.y]);
        float w6 = __ldg(&g_f2[cb.z]), w7 = __ldg(&g_f2[cb.w]);
        float4 v0 = ldrow_h(g_seqh + (size_t)ca.x * DOUT, lane);
        float4 v1 = ldrow_h(g_seqh + (size_t)ca.y * DOUT, lane);
        float4 v2 = ldrow_h(g_seqh + (size_t)ca.z * DOUT, lane);
        float4 v3 = ldrow_h(g_seqh + (size_t)ca.w * DOUT, lane);
        float4 v4 = ldrow_h(g_seqh + (size_t)cb.x * DOUT, lane);
        float4 v5 = ldrow_h(g_seqh + (size_t)cb.y * DOUT, lane);
        float4 v6 = ldrow_h(g_seqh + (size_t)cb.z * DOUT, lane);
        float4 v7 = ldrow_h(g_seqh + (size_t)cb.w * DOUT, lane);
        float e0 = edge_e(f1v + w0);
        float e1 = edge_e(f1v + w1);
        float e2 = edge_e(f1v + w2);
        float e3 = edge_e(f1v + w3);
        float e4 = edge_e(f1v + w4);
        float e5 = edge_e(f1v + w5);
        float e6 = edge_e(f1v + w6);
        float e7 = edge_e(f1v + w7);
        ssum += ((e0 + e1) + (e2 + e3)) + ((e4 + e5) + (e6 + e7));
        acc.x += e0 * v0.x + e1 * v1.x + e2 * v2.x + e3 * v3.x
               + e4 * v4.x + e5 * v5.x + e6 * v6.x + e7 * v7.x;
        acc.y += e0 * v0.y + e1 * v1.y + e2 * v2.y + e3 * v3.y
               + e4 * v4.y + e5 * v5.y + e6 * v6.y + e7 * v7.y;
        acc.z += e0 * v0.z + e1 * v1.z + e2 * v2.z + e3 * v3.z
               + e4 * v4.z + e5 * v5.z + e6 * v6.z + e7 * v7.z;
        acc.w += e0 * v0.w + e1 * v1.w + e2 * v2.w + e3 * v3.w
               + e4 * v4.w + e5 * v5.w + e6 * v6.w + e7 * v7.w;
    }
    for (; j < end; j++) {
        int c = __ldg(&g_ecol[j]);
        float ev = edge_e(f1v + __ldg(&g_f2[c]));
        ssum += ev;
        EDGE_ACC(c, ev);
    }

    float inv = (end > j0) ? 1.0f / ssum : 0.0f;
    float4 b = ((const float4*)bias)[lane];
    acc.x = acc.x * inv + b.x;
    acc.y = acc.y * inv + b.y;
    acc.z = acc.z * inv + b.z;
    acc.w = acc.w * inv + b.w;
    ((float4*)(out + (size_t)gw * DOUT))[lane] = acc;
}

// ---------------------------------------------------------------------------
extern "C" void kernel_launch(void* const* d_in, const int* in_sizes, int n_in,
                              void* d_out, int out_size) {
    const float* feat = (const float*)d_in[0];
    const int*   row  = (const int*)  d_in[1];
    const int*   col  = (const int*)  d_in[2];
    const float* W    = (const float*)d_in[3];
    const float* al_w = (const float*)d_in[4];
    const float* al_b = (const float*)d_in[5];
    const float* ar_w = (const float*)d_in[6];
    const float* ar_b = (const float*)d_in[7];
    const float* bias = (const float*)d_in[8];
    float* out = (float*)d_out;

    int n = in_sizes[0] / DIN;   // 100000
    int e = in_sizes[1];         // 3200000
    int nblk = (n + 255) / 256;          // scan blocks (<= 512)
    int eblk = (e / 4 + 255) / 256;      // edge-pass blocks (3125)
    int GB   = (n + 127) / 128;          // gemm blocks (782)

    k_combo1<<<WCONV_BLOCKS + eblk, 256>>>(W, row, e);            // wconv + edge1
    k_scan1<<<nblk, 256>>>(n);
    k_scan23<<<(n + 511) / 512, 512>>>(n, nblk);
    k_combo2<<<GB + eblk, 256>>>(feat, al_w, al_b, ar_w, ar_b,    // gemm + edge2
                                 row, col, n, e, GB);
    k_spmm<<<(n * 32 + 255) / 256, 256>>>(bias, out, n);
}